// round 1
// baseline (speedup 1.0000x reference)
#include <cuda_runtime.h>
#include <cuda_bf16.h>
#include <cstddef>

// Problem constants
#define BATCH 4
#define C     64
#define H     512
#define W     512
#define LAT   256
#define TH    16
#define TW    16
#define SR    18      // tile + halo
#define CI    32      // input-channel chunk held in smem

// Scratch (module-load allocated, not runtime alloc)
__device__ float g_wm0[BATCH * C * 9 * C];
__device__ float g_wm1[BATCH * C * 9 * C];
__device__ float g_mid[(size_t)BATCH * C * H * W];

__device__ __forceinline__ int refl(int v) {
    return v < 0 ? -v : (v > H - 1 ? 2 * (H - 1) - v : v);
}

__device__ __forceinline__ void fma2(unsigned long long& acc,
                                     unsigned long long a,
                                     unsigned long long b) {
    asm("fma.rn.f32x2 %0, %1, %2, %0;" : "+l"(acc) : "l"(a), "l"(b));
}

__device__ __forceinline__ unsigned long long pack2(float x) {
    unsigned long long r;
    asm("mov.b64 %0, {%1, %1};" : "=l"(r) : "f"(x));
    return r;
}

// ---------------------------------------------------------------------------
// Prep: fold EqualLinear modulation + demodulation into per-batch weights.
//   s[b][i]   = 1 + sqrt(2/LAT) * <latent[b], mw[i]> + mb[i]
//   d[b][o]   = rsqrt( sum_i s^2 * wscale^2*sum_t w[o][i][t]^2 + 1e-5 )
//   Wm[b][i][t][o] = d[b][o] * s[b][i] * w[o][i][t] * wscale
// Layout: o contiguous (for paired LDS.64 in the conv).
// ---------------------------------------------------------------------------
template <int PASS>
__global__ void prep_kernel(const float* __restrict__ latent,
                            const float* __restrict__ w,
                            const float* __restrict__ mw,
                            const float* __restrict__ mb) {
    float* gwm = (PASS == 0) ? g_wm0 : g_wm1;
    __shared__ float s[C];
    __shared__ float d[C];
    const int b = blockIdx.x;
    const int t = threadIdx.x;
    const float lscale = 0.08838834764831845f;   // sqrt(2/256)
    const float wscale = 0.05892556509887896f;   // sqrt(2/576)

    if (t < C) {
        float acc = 0.f;
        const float* lb  = latent + b * LAT;
        const float* mwr = mw + t * LAT;
        #pragma unroll 4
        for (int l = 0; l < LAT; ++l) acc += lb[l] * mwr[l];
        s[t] = 1.f + acc * lscale + mb[t];
    }
    __syncthreads();
    if (t < C) {
        float acc = 0.f;
        for (int i = 0; i < C; ++i) {
            float wsq = 0.f;
            const float* wr = w + (t * C + i) * 9;
            #pragma unroll
            for (int k = 0; k < 9; ++k) { float v = wr[k]; wsq += v * v; }
            acc += s[i] * s[i] * wsq;
        }
        d[t] = rsqrtf(acc * wscale * wscale + 1e-5f);
    }
    __syncthreads();
    for (int idx = t; idx < C * 9 * C; idx += blockDim.x) {
        int o = idx & 63;
        int k = (idx >> 6) % 9;
        int i = idx / (9 * 64);
        gwm[b * C * 9 * C + idx] = d[o] * s[i] * w[(o * C + i) * 9 + k] * wscale;
    }
}

// ---------------------------------------------------------------------------
// Direct conv 3x3, reflect pad, + bias + leakyrelu(0.2)*sqrt(2).
// Block: 16x16 output tile, one batch item, all 64 output channels.
// 512 threads: t = og*128 + p ; og in 0..3 -> 16 output channels each;
//              p -> pixel (py, px) plus second pixel (py+8, px).
// Inner loop: broadcast LDS.64 weight pair + 2x fma.rn.f32x2 (FMA-pipe bound).
// ---------------------------------------------------------------------------
template <int PASS>
__global__ void __launch_bounds__(512, 1)
conv_kernel(const float* __restrict__ xin,
            const float* __restrict__ bias,
            float* __restrict__ xout) {
    const float* src = (PASS == 0) ? xin : g_mid;
    const float* wm  = (PASS == 0) ? g_wm0 : g_wm1;
    float* dst       = (PASS == 0) ? g_mid : xout;

    extern __shared__ float sm[];
    float* sx = sm;                    // [C][SR*SR]
    float* sw = sm + C * SR * SR;      // [CI*9*64]

    const int b  = blockIdx.z;
    const int y0 = blockIdx.y * TH;
    const int x0 = blockIdx.x * TW;
    const int t  = threadIdx.x;
    const int p  = t & 127;
    const int og = t >> 7;             // 0..3
    const int py = p >> 4;             // 0..7 (rows py and py+8)
    const int px = p & 15;
    const int obase = og * 16;

    const size_t plane = (size_t)H * W;
    const float* srcb = src + (size_t)b * C * plane;

    // Load input tile with reflect-pad halo
    for (int idx = t; idx < C * SR * SR; idx += 512) {
        int c   = idx / (SR * SR);
        int rem = idx - c * (SR * SR);
        int r   = rem / SR;
        int cc  = rem - r * SR;
        int gy  = refl(y0 + r - 1);
        int gx  = refl(x0 + cc - 1);
        sx[idx] = srcb[c * plane + (size_t)gy * W + gx];
    }

    unsigned long long accA[8], accB[8];
    #pragma unroll
    for (int q = 0; q < 8; ++q) { accA[q] = 0ull; accB[q] = 0ull; }

    for (int ch = 0; ch < C; ch += CI) {
        __syncthreads();
        const float* wsrc = wm + ((size_t)b * C + ch) * 9 * 64;
        for (int idx = t; idx < CI * 9 * 64; idx += 512) sw[idx] = wsrc[idx];
        __syncthreads();

        #pragma unroll 1
        for (int i = 0; i < CI; ++i) {
            const float* sxc = sx + (ch + i) * (SR * SR);
            #pragma unroll
            for (int tap = 0; tap < 9; ++tap) {
                const int ky = tap / 3;
                const int kx = tap - 3 * ky;
                float xa = sxc[(py + ky) * SR + px + kx];
                float xb = sxc[(py + 8 + ky) * SR + px + kx];
                unsigned long long xa2 = pack2(xa);
                unsigned long long xb2 = pack2(xb);
                const float* swp = sw + (i * 9 + tap) * 64 + obase;
                #pragma unroll
                for (int q = 0; q < 8; ++q) {
                    unsigned long long w2 =
                        *reinterpret_cast<const unsigned long long*>(swp + 2 * q);
                    fma2(accA[q], w2, xa2);
                    fma2(accB[q], w2, xb2);
                }
            }
        }
    }

    // Epilogue: + bias, leaky-relu * sqrt(2), store
    const float gain = 1.4142135623730951f;
    #pragma unroll
    for (int q = 0; q < 8; ++q) {
        const int o = obase + 2 * q;
        float v0 = __uint_as_float((unsigned)(accA[q] & 0xffffffffull));
        float v1 = __uint_as_float((unsigned)(accA[q] >> 32));
        float v2 = __uint_as_float((unsigned)(accB[q] & 0xffffffffull));
        float v3 = __uint_as_float((unsigned)(accB[q] >> 32));
        const float bo0 = bias[o], bo1 = bias[o + 1];
        v0 += bo0; v1 += bo1; v2 += bo0; v3 += bo1;
        v0 = (v0 >= 0.f ? v0 : 0.2f * v0) * gain;
        v1 = (v1 >= 0.f ? v1 : 0.2f * v1) * gain;
        v2 = (v2 >= 0.f ? v2 : 0.2f * v2) * gain;
        v3 = (v3 >= 0.f ? v3 : 0.2f * v3) * gain;
        float* d0 = dst + ((size_t)(b * C + o) * H + y0 + py) * W + x0 + px;
        float* d1 = dst + ((size_t)(b * C + o + 1) * H + y0 + py) * W + x0 + px;
        d0[0] = v0;
        d1[0] = v1;
        d0[(size_t)8 * W] = v2;
        d1[(size_t)8 * W] = v3;
    }
}

extern "C" void kernel_launch(void* const* d_in, const int* in_sizes, int n_in,
                              void* d_out, int out_size) {
    const float* x      = (const float*)d_in[0];
    const float* latent = (const float*)d_in[1];
    const float* w0     = (const float*)d_in[2];
    const float* b0     = (const float*)d_in[3];
    const float* mw0    = (const float*)d_in[4];
    const float* mb0    = (const float*)d_in[5];
    const float* w1     = (const float*)d_in[6];
    const float* b1     = (const float*)d_in[7];
    const float* mw1    = (const float*)d_in[8];
    const float* mb1    = (const float*)d_in[9];
    float* out = (float*)d_out;

    const int smem = (C * SR * SR + CI * 9 * 64) * 4;  // 156672 B
    cudaFuncSetAttribute(conv_kernel<0>,
                         cudaFuncAttributeMaxDynamicSharedMemorySize, smem);
    cudaFuncSetAttribute(conv_kernel<1>,
                         cudaFuncAttributeMaxDynamicSharedMemorySize, smem);

    prep_kernel<0><<<BATCH, 256>>>(latent, w0, mw0, mb0);
    prep_kernel<1><<<BATCH, 256>>>(latent, w1, mw1, mb1);

    dim3 grid(W / TW, H / TH, BATCH);
    conv_kernel<0><<<grid, 512, smem>>>(x, b0, nullptr);
    conv_kernel<1><<<grid, 512, smem>>>(nullptr, b1, out);
}